// round 1
// baseline (speedup 1.0000x reference)
#include <cuda_runtime.h>
#include <math.h>

#define N_CELLS 512
#define N_GENES 256
#define D 128
#define HEADS 4
#define HD 32
#define E_SP 8192
#define E_GRN 2048

// ---------------- scratch (device globals: allocation-free) ----------------
__device__ float g_agg[N_CELLS * D];
__device__ float g_high_out[N_CELLS * D];
__device__ float g_q[N_CELLS * N_GENES * D];
__device__ float g_k[N_CELLS * N_GENES * D];
__device__ float g_v[N_CELLS * N_GENES * D];
__device__ float g_skip[N_CELLS * N_GENES * D];
__device__ float g_attn[N_CELLS * N_GENES * D];
__device__ float g_low_out[N_CELLS * N_GENES * D];
__device__ float g_gene_sum[N_CELLS * D];
__device__ float g_gene_agg[N_CELLS * D];
__device__ float g_low_cross[N_CELLS * D];
__device__ int g_off[N_GENES + 1];
__device__ int g_srcs[E_GRN];

// ---------------- helpers ----------------
__device__ __forceinline__ float geluf(float x) {
    return 0.5f * x * (1.f + erff(x * 0.7071067811865476f));
}
__device__ __forceinline__ float sigmoidf_(float x) {
    return 1.f / (1.f + expf(-x));
}
__device__ __forceinline__ float warpSum(float v) {
#pragma unroll
    for (int o = 16; o; o >>= 1) v += __shfl_xor_sync(0xffffffffu, v, o);
    return v;
}
__device__ __forceinline__ float warpMax(float v) {
#pragma unroll
    for (int o = 16; o; o >>= 1) v = fmaxf(v, __shfl_xor_sync(0xffffffffu, v, o));
    return v;
}

// ---------------- K0: zero spatial agg ----------------
__global__ void k_zero() {
    int i = blockIdx.x * blockDim.x + threadIdx.x;
    if (i < N_CELLS * D) g_agg[i] = 0.f;
}

// ---------------- K1: spatial scatter-add ----------------
__global__ void k_scatter(const float* __restrict__ high, const int* __restrict__ sp) {
    int idx = blockIdx.x * blockDim.x + threadIdx.x;
    if (idx >= E_SP * D) return;
    int e = idx >> 7, d = idx & 127;
    int s = sp[e];
    int t = sp[E_SP + e];
    atomicAdd(&g_agg[t * D + d], high[s * D + d]);
}

// ---------------- K2: build CSR over grn edges (shared across cells) -------
__global__ void k_csr(const int* __restrict__ grn) {
    __shared__ int cnt[N_GENES];
    __shared__ int cur[N_GENES];
    int tid = threadIdx.x;
    if (tid < N_GENES) cnt[tid] = 0;
    __syncthreads();
    for (int e = tid; e < E_GRN; e += blockDim.x) atomicAdd(&cnt[grn[E_GRN + e]], 1);
    __syncthreads();
    if (tid == 0) {
        int run = 0;
        for (int g = 0; g < N_GENES; ++g) {
            g_off[g] = run;
            cur[g] = run;
            run += cnt[g];
        }
        g_off[N_GENES] = run;
    }
    __syncthreads();
    for (int e = tid; e < E_GRN; e += blockDim.x) {
        int dg = grn[E_GRN + e];
        int p = atomicAdd(&cur[dg], 1);
        g_srcs[p] = grn[e];
    }
}

// ---------------- K3: GIN MLP + LN -> high_out ----------------
__global__ void k_gin(const float* __restrict__ high,
                      const float* __restrict__ w1, const float* __restrict__ b1,
                      const float* __restrict__ w2, const float* __restrict__ b2,
                      const float* __restrict__ epsp,
                      const float* __restrict__ lng, const float* __restrict__ lnb) {
    __shared__ float x[D];
    __shared__ float hid[2 * D];
    __shared__ float r1[D], r2[D];
    int c = blockIdx.x, tid = threadIdx.x;
    float ep = 1.f + epsp[0];
    if (tid < D) x[tid] = ep * high[c * D + tid] + g_agg[c * D + tid];
    __syncthreads();
    float t = b1[tid];
#pragma unroll 4
    for (int k = 0; k < D; ++k) t = fmaf(x[k], w1[k * 2 * D + tid], t);
    hid[tid] = geluf(t);
    __syncthreads();
    float o = 0.f;
    if (tid < D) {
        o = b2[tid];
#pragma unroll 4
        for (int k = 0; k < 2 * D; ++k) o = fmaf(hid[k], w2[k * D + tid], o);
        r1[tid] = o;
        r2[tid] = o * o;
    }
    __syncthreads();
    for (int s = 64; s >= 1; s >>= 1) {
        if (tid < s) { r1[tid] += r1[tid + s]; r2[tid] += r2[tid + s]; }
        __syncthreads();
    }
    float mean = r1[0] * (1.f / D);
    float var = r2[0] * (1.f / D) - mean * mean;
    float inv = rsqrtf(var + 1e-5f);
    if (tid < D) g_high_out[c * D + tid] = (o - mean) * inv * lng[tid] + lnb[tid];
}

// ---------------- K4: fused 4-way projection GEMM ----------------
// A(131072x128) x {wq,wk,wv,wskip}(128x128) + bias -> g_q/g_k/g_v/g_skip
// Block tile: 128 rows x 128 cols, thread tile 8x8, A staged k-major (pad 129).
__global__ void __launch_bounds__(256) k_proj(const float* __restrict__ A,
        const float* __restrict__ wq, const float* __restrict__ wk,
        const float* __restrict__ wv, const float* __restrict__ ws,
        const float* __restrict__ bq, const float* __restrict__ bk,
        const float* __restrict__ bv, const float* __restrict__ bs) {
    extern __shared__ float sm[];
    float* As = sm;             // [128][129] k-major
    float* Bs = sm + 128 * 129; // [128][128]
    int tid = threadIdx.x;
    int tx = tid & 15, ty = tid >> 4;
    int row0 = blockIdx.x * 128;

    for (int i = tid; i < 128 * 32; i += 256) {
        int r = i >> 5, c4 = i & 31;
        float4 v = *(const float4*)(A + (size_t)(row0 + r) * 128 + c4 * 4);
        As[(c4 * 4 + 0) * 129 + r] = v.x;
        As[(c4 * 4 + 1) * 129 + r] = v.y;
        As[(c4 * 4 + 2) * 129 + r] = v.z;
        As[(c4 * 4 + 3) * 129 + r] = v.w;
    }
    const float* Ws[4] = {wq, wk, wv, ws};
    const float* Bias[4] = {bq, bk, bv, bs};
    float* Outs[4] = {g_q, g_k, g_v, g_skip};

    for (int w = 0; w < 4; ++w) {
        __syncthreads();
        {
            const float4* Wv = (const float4*)Ws[w];
            float4* Bv = (float4*)Bs;
            for (int i = tid; i < 128 * 32; i += 256) Bv[i] = Wv[i];
        }
        __syncthreads();
        float acc[8][8];
#pragma unroll
        for (int i = 0; i < 8; i++)
#pragma unroll
            for (int j = 0; j < 8; j++) acc[i][j] = 0.f;

#pragma unroll 2
        for (int k = 0; k < 128; ++k) {
            float a[8];
#pragma unroll
            for (int i = 0; i < 8; i++) a[i] = As[k * 129 + ty * 8 + i];
            float4 b0 = *(float4*)(Bs + k * 128 + tx * 4);
            float4 b1 = *(float4*)(Bs + k * 128 + 64 + tx * 4);
            float b[8] = {b0.x, b0.y, b0.z, b0.w, b1.x, b1.y, b1.z, b1.w};
#pragma unroll
            for (int i = 0; i < 8; i++) {
#pragma unroll
                for (int j = 0; j < 8; j++) acc[i][j] = fmaf(a[i], b[j], acc[i][j]);
            }
        }
        const float* bias = Bias[w];
        float4 bb0 = *(const float4*)(bias + tx * 4);
        float4 bb1 = *(const float4*)(bias + 64 + tx * 4);
        float* Out = Outs[w];
#pragma unroll
        for (int i = 0; i < 8; i++) {
            size_t r = (size_t)row0 + ty * 8 + i;
            float4 o0 = make_float4(acc[i][0] + bb0.x, acc[i][1] + bb0.y,
                                    acc[i][2] + bb0.z, acc[i][3] + bb0.w);
            float4 o1 = make_float4(acc[i][4] + bb1.x, acc[i][5] + bb1.y,
                                    acc[i][6] + bb1.z, acc[i][7] + bb1.w);
            *(float4*)(Out + r * 128 + tx * 4) = o0;
            *(float4*)(Out + r * 128 + 64 + tx * 4) = o1;
        }
    }
}

// ---------------- K5: per-cell GRN attention ----------------
// Block = cell (512 blocks, 256 thr). Per head: stage q/k/v head-slices in smem
// (stride 33 kills bank conflicts), warp-per-gene online softmax over CSR edges.
__global__ void __launch_bounds__(256) k_attn() {
    extern __shared__ float sm[];
    float* qs = sm;
    float* ks = qs + N_GENES * 33;
    float* vs = ks + N_GENES * 33;
    int* soff = (int*)(vs + N_GENES * 33);
    int* ssrc = soff + 260;
    int c = blockIdx.x, tid = threadIdx.x;
    int lane = tid & 31, warp = tid >> 5;
    for (int i = tid; i <= N_GENES; i += 256) soff[i] = g_off[i];
    for (int i = tid; i < E_GRN; i += 256) ssrc[i] = g_srcs[i];
    const float* qb = g_q + (size_t)c * N_GENES * D;
    const float* kb = g_k + (size_t)c * N_GENES * D;
    const float* vb = g_v + (size_t)c * N_GENES * D;
    float* ob = g_attn + (size_t)c * N_GENES * D;

    for (int h = 0; h < HEADS; ++h) {
        __syncthreads();
        int hb = h * HD;
        for (int i = tid; i < N_GENES * HD; i += 256) {
            int g = i >> 5, d = i & 31;
            qs[g * 33 + d] = qb[g * D + hb + d];
            ks[g * 33 + d] = kb[g * D + hb + d];
            vs[g * 33 + d] = vb[g * D + hb + d];
        }
        __syncthreads();
        for (int g = warp; g < N_GENES; g += 8) {
            int o0 = soff[g], o1 = soff[g + 1];
            float out = 0.f;
            if (o1 > o0) {
                float m = -3.4e38f, s = 0.f, acc = 0.f;
                const float* qg = qs + g * 33;
                for (int base = o0; base < o1; base += 32) {
                    int cnt = min(32, o1 - base);
                    float logit = -3.4e38f;
                    int sj = 0;
                    if (lane < cnt) {
                        sj = ssrc[base + lane];
                        const float* kr = ks + sj * 33;
                        float t = 0.f;
#pragma unroll
                        for (int d = 0; d < HD; ++d) t = fmaf(qg[d], kr[d], t);
                        logit = t * 0.17677669529663689f;  // 1/sqrt(32)
                    }
                    float nm = fmaxf(m, warpMax(logit));
                    float sc = expf(m - nm);  // 0 on first chunk (m = -3.4e38)
                    s *= sc;
                    acc *= sc;
                    float e = (lane < cnt) ? expf(logit - nm) : 0.f;
                    s += warpSum(e);
                    for (int jj = 0; jj < cnt; ++jj) {
                        float ej = __shfl_sync(0xffffffffu, e, jj);
                        int sjj = __shfl_sync(0xffffffffu, sj, jj);
                        acc = fmaf(ej, vs[sjj * 33 + lane], acc);
                    }
                    m = nm;
                }
                out = acc / s;
            }
            ob[g * D + hb + lane] = out;
        }
    }
}

// ---------------- K6: low_out = LN(attn + skip), plus per-cell gene sum ----
__global__ void k_lowout(const float* __restrict__ lng, const float* __restrict__ lnb) {
    __shared__ float part[4 * D];
    int c = blockIdx.x, tid = threadIdx.x;
    int lane = tid & 31, warp = tid >> 5;
    float4 gg = *(const float4*)(lng + lane * 4);
    float4 bb = *(const float4*)(lnb + lane * 4);
    float4 ls = make_float4(0.f, 0.f, 0.f, 0.f);
    const float* ab = g_attn + (size_t)c * N_GENES * D;
    const float* sb = g_skip + (size_t)c * N_GENES * D;
    float* lo = g_low_out + (size_t)c * N_GENES * D;
    for (int g = warp; g < N_GENES; g += 4) {
        float4 a = *(const float4*)(ab + g * D + lane * 4);
        float4 sk = *(const float4*)(sb + g * D + lane * 4);
        float4 x = make_float4(a.x + sk.x, a.y + sk.y, a.z + sk.z, a.w + sk.w);
        float sum = warpSum(x.x + x.y + x.z + x.w);
        float sq = warpSum(x.x * x.x + x.y * x.y + x.z * x.z + x.w * x.w);
        float mean = sum * (1.f / D);
        float var = sq * (1.f / D) - mean * mean;
        float inv = rsqrtf(var + 1e-5f);
        float4 y;
        y.x = (x.x - mean) * inv * gg.x + bb.x;
        y.y = (x.y - mean) * inv * gg.y + bb.y;
        y.z = (x.z - mean) * inv * gg.z + bb.z;
        y.w = (x.w - mean) * inv * gg.w + bb.w;
        *(float4*)(lo + g * D + lane * 4) = y;
        ls.x += y.x; ls.y += y.y; ls.z += y.z; ls.w += y.w;
    }
    part[warp * D + lane * 4 + 0] = ls.x;
    part[warp * D + lane * 4 + 1] = ls.y;
    part[warp * D + lane * 4 + 2] = ls.z;
    part[warp * D + lane * 4 + 3] = ls.w;
    __syncthreads();
    if (tid < D) {
        float s = part[tid] + part[D + tid] + part[2 * D + tid] + part[3 * D + tid];
        g_gene_sum[c * D + tid] = s;
    }
}

// ---------------- K7: gene_agg = gelu(mean @ agg_w + agg_b) ----------------
__global__ void k_geneagg(const float* __restrict__ aw, const float* __restrict__ ab_) {
    __shared__ float m[D];
    int c = blockIdx.x, tid = threadIdx.x;
    m[tid] = g_gene_sum[c * D + tid] * (1.f / N_GENES);
    __syncthreads();
    float t = ab_[tid];
#pragma unroll 4
    for (int k = 0; k < D; ++k) t = fmaf(m[k], aw[k * D + tid], t);
    g_gene_agg[c * D + tid] = geluf(t);
}

// ---------------- K8: cross gating + high_new ----------------
__global__ void k_cross(const float* __restrict__ high_emb,
                        const float* __restrict__ cw, const float* __restrict__ cb,
                        const float* __restrict__ nhg, const float* __restrict__ nhb,
                        float* __restrict__ out_high) {
    __shared__ float hs[D], gs[D];
    __shared__ float r1[D], r2[D];
    int c = blockIdx.x, tid = threadIdx.x;
    float ho = g_high_out[c * D + tid];
    hs[tid] = ho;
    gs[tid] = g_gene_agg[c * D + tid];
    __syncthreads();
    float q1 = cb[tid], k1 = cb[D + tid], v1 = cb[2 * D + tid];
    float q2 = cb[3 * D + tid], k2 = cb[4 * D + tid], v2 = cb[5 * D + tid];
#pragma unroll 2
    for (int k = 0; k < D; ++k) {
        float hv = hs[k], gv = gs[k];
        const float* cwk = cw + k * D + tid;
        q1 = fmaf(hv, cwk[0], q1);
        k1 = fmaf(gv, cwk[16384], k1);
        v1 = fmaf(gv, cwk[32768], v1);
        q2 = fmaf(gv, cwk[49152], q2);
        k2 = fmaf(hv, cwk[65536], k2);
        v2 = fmaf(hv, cwk[81920], v2);
    }
    r1[tid] = q1 * k1;
    r2[tid] = q2 * k2;
    __syncthreads();
    for (int s = 64; s >= 1; s >>= 1) {
        if (tid < s) { r1[tid] += r1[tid + s]; r2[tid] += r2[tid + s]; }
        __syncthreads();
    }
    const float sc = 0.08838834764831845f;  // 128^-0.5
    float g1 = sigmoidf_(r1[0] * sc);
    float g2 = sigmoidf_(r2[0] * sc);
    g_low_cross[c * D + tid] = g2 * v2;
    float x = high_emb[c * D + tid] + ho + g1 * v1;
    __syncthreads();
    r1[tid] = x;
    r2[tid] = x * x;
    __syncthreads();
    for (int s = 64; s >= 1; s >>= 1) {
        if (tid < s) { r1[tid] += r1[tid + s]; r2[tid] += r2[tid + s]; }
        __syncthreads();
    }
    float mean = r1[0] * (1.f / D);
    float var = r2[0] * (1.f / D) - mean * mean;
    out_high[c * D + tid] = (x - mean) * rsqrtf(var + 1e-5f) * nhg[tid] + nhb[tid];
}

// ---------------- K9: low_new = LN(low_emb + low_out + low_cross) ----------
__global__ void k_lownew(const float* __restrict__ low_emb,
                         const float* __restrict__ nlg, const float* __restrict__ nlb,
                         float* __restrict__ out_low) {
    int tid = threadIdx.x, lane = tid & 31, warp = tid >> 5;
    int row = blockIdx.x * 8 + warp;  // 0..131071
    int c = row >> 8;
    float4 gg = *(const float4*)(nlg + lane * 4);
    float4 bb = *(const float4*)(nlb + lane * 4);
    float4 le = *(const float4*)(low_emb + (size_t)row * D + lane * 4);
    float4 lo = *(const float4*)(g_low_out + (size_t)row * D + lane * 4);
    float4 lc = *(const float4*)(g_low_cross + c * D + lane * 4);
    float4 x = make_float4(le.x + lo.x + lc.x, le.y + lo.y + lc.y,
                           le.z + lo.z + lc.z, le.w + lo.w + lc.w);
    float sum = warpSum(x.x + x.y + x.z + x.w);
    float sq = warpSum(x.x * x.x + x.y * x.y + x.z * x.z + x.w * x.w);
    float mean = sum * (1.f / D);
    float var = sq * (1.f / D) - mean * mean;
    float inv = rsqrtf(var + 1e-5f);
    float4 y;
    y.x = (x.x - mean) * inv * gg.x + bb.x;
    y.y = (x.y - mean) * inv * gg.y + bb.y;
    y.z = (x.z - mean) * inv * gg.z + bb.z;
    y.w = (x.w - mean) * inv * gg.w + bb.w;
    *(float4*)(out_low + (size_t)row * D + lane * 4) = y;
}

// ---------------- host ----------------
extern "C" void kernel_launch(void* const* d_in, const int* in_sizes, int n_in,
                              void* d_out, int out_size) {
    const float* high = (const float*)d_in[0];
    const float* low = (const float*)d_in[1];
    const int* sp = (const int*)d_in[2];
    const int* grn = (const int*)d_in[3];
    const float* gin_w1 = (const float*)d_in[4];
    const float* gin_b1 = (const float*)d_in[5];
    const float* gin_w2 = (const float*)d_in[6];
    const float* gin_b2 = (const float*)d_in[7];
    const float* gin_eps = (const float*)d_in[8];
    const float* gin_lng = (const float*)d_in[9];
    const float* gin_lnb = (const float*)d_in[10];
    const float* wq = (const float*)d_in[11];
    const float* bq = (const float*)d_in[12];
    const float* wk = (const float*)d_in[13];
    const float* bk = (const float*)d_in[14];
    const float* wv = (const float*)d_in[15];
    const float* bv = (const float*)d_in[16];
    const float* wsk = (const float*)d_in[17];
    const float* bsk = (const float*)d_in[18];
    const float* tclng = (const float*)d_in[19];
    const float* tclnb = (const float*)d_in[20];
    const float* cw = (const float*)d_in[21];
    const float* cb = (const float*)d_in[22];
    const float* aw = (const float*)d_in[23];
    const float* ab = (const float*)d_in[24];
    const float* nhg = (const float*)d_in[25];
    const float* nhb = (const float*)d_in[26];
    const float* nlg = (const float*)d_in[27];
    const float* nlb = (const float*)d_in[28];

    float* out_high = (float*)d_out;
    float* out_low = out_high + N_CELLS * D;

    int smem_proj = (128 * 129 + 128 * 128) * (int)sizeof(float);
    cudaFuncSetAttribute(k_proj, cudaFuncAttributeMaxDynamicSharedMemorySize, smem_proj);
    int smem_attn = (3 * N_GENES * 33) * (int)sizeof(float) + (260 + E_GRN) * (int)sizeof(int);
    cudaFuncSetAttribute(k_attn, cudaFuncAttributeMaxDynamicSharedMemorySize, smem_attn);

    k_zero<<<64, 1024>>>();
    k_scatter<<<(E_SP * D) / 256, 256>>>(high, sp);
    k_csr<<<1, 256>>>(grn);
    k_gin<<<N_CELLS, 256>>>(high, gin_w1, gin_b1, gin_w2, gin_b2, gin_eps, gin_lng, gin_lnb);
    k_proj<<<(N_CELLS * N_GENES) / 128, 256, smem_proj>>>(low, wq, wk, wv, wsk, bq, bk, bv, bsk);
    k_attn<<<N_CELLS, 256, smem_attn>>>();
    k_lowout<<<N_CELLS, 128>>>(tclng, tclnb);
    k_geneagg<<<N_CELLS, 128>>>(aw, ab);
    k_cross<<<N_CELLS, 128>>>(high, cw, cb, nhg, nhb, out_high);
    k_lownew<<<(N_CELLS * N_GENES) / 8, 256>>>(low, nlg, nlb, out_low);
}

// round 3
// speedup vs baseline: 1.3100x; 1.3100x over previous
#include <cuda_runtime.h>
#include <cstdint>
#include <mma.h>
#include <math.h>

using namespace nvcuda;

#define N_CELLS 512
#define N_GENES 256
#define D 128
#define HEADS 4
#define HD 32
#define E_SP 8192
#define E_GRN 2048

#define PAD_A 132
#define PAD_B 136

// ---------------- scratch (device globals: allocation-free) ----------------
__device__ float g_agg[N_CELLS * D];
__device__ float g_high_out[N_CELLS * D];
__device__ float g_q[N_CELLS * N_GENES * D];
__device__ float g_k[N_CELLS * N_GENES * D];
__device__ float g_v[N_CELLS * N_GENES * D];
__device__ float g_skip[N_CELLS * N_GENES * D];
__device__ float g_attn[N_CELLS * N_GENES * D];
__device__ float g_low_out[N_CELLS * N_GENES * D];
__device__ float g_gene_sum[N_CELLS * D];
__device__ float g_gene_agg[N_CELLS * D];
__device__ float g_low_cross[N_CELLS * D];
__device__ int g_off[N_GENES + 1];
__device__ int g_srcs[E_GRN];

// ---------------- helpers ----------------
__device__ __forceinline__ float geluf(float x) {
    return 0.5f * x * (1.f + erff(x * 0.7071067811865476f));
}
__device__ __forceinline__ float sigmoidf_(float x) {
    return 1.f / (1.f + expf(-x));
}
__device__ __forceinline__ float warpSum(float v) {
#pragma unroll
    for (int o = 16; o; o >>= 1) v += __shfl_xor_sync(0xffffffffu, v, o);
    return v;
}
__device__ __forceinline__ float warpMax(float v) {
#pragma unroll
    for (int o = 16; o; o >>= 1) v = fmaxf(v, __shfl_xor_sync(0xffffffffu, v, o));
    return v;
}
__device__ __forceinline__ void cp16(void* smem, const void* g) {
    unsigned s = (unsigned)__cvta_generic_to_shared(smem);
    asm volatile("cp.async.cg.shared.global [%0], [%1], 16;\n" :: "r"(s), "l"(g));
}
#define CP_COMMIT() asm volatile("cp.async.commit_group;\n" ::: "memory")
#define CP_WAIT0()  asm volatile("cp.async.wait_group 0;\n" ::: "memory")

// ---------------- K0: zero spatial agg ----------------
__global__ void k_zero() {
    int i = blockIdx.x * blockDim.x + threadIdx.x;
    if (i < N_CELLS * D) g_agg[i] = 0.f;
}

// ---------------- K1: spatial scatter-add ----------------
__global__ void k_scatter(const float* __restrict__ high, const int* __restrict__ sp) {
    int idx = blockIdx.x * blockDim.x + threadIdx.x;
    if (idx >= E_SP * D) return;
    int e = idx >> 7, d = idx & 127;
    int s = sp[e];
    int t = sp[E_SP + e];
    atomicAdd(&g_agg[t * D + d], high[s * D + d]);
}

// ---------------- K2: build CSR over grn edges ----------------
__global__ void k_csr(const int* __restrict__ grn) {
    __shared__ int cnt[N_GENES];
    __shared__ int cur[N_GENES];
    int tid = threadIdx.x;
    if (tid < N_GENES) cnt[tid] = 0;
    __syncthreads();
    for (int e = tid; e < E_GRN; e += blockDim.x) atomicAdd(&cnt[grn[E_GRN + e]], 1);
    __syncthreads();
    if (tid == 0) {
        int run = 0;
        for (int g = 0; g < N_GENES; ++g) {
            g_off[g] = run;
            cur[g] = run;
            run += cnt[g];
        }
        g_off[N_GENES] = run;
    }
    __syncthreads();
    for (int e = tid; e < E_GRN; e += blockDim.x) {
        int dg = grn[E_GRN + e];
        int p = atomicAdd(&cur[dg], 1);
        g_srcs[p] = grn[e];
    }
}

// ---------------- K3: GIN MLP + LN, 8 cells/block ----------------
__global__ void __launch_bounds__(256) k_gin(const float* __restrict__ high,
                      const float* __restrict__ w1, const float* __restrict__ b1,
                      const float* __restrict__ w2, const float* __restrict__ b2,
                      const float* __restrict__ epsp,
                      const float* __restrict__ lng, const float* __restrict__ lnb) {
    __shared__ float xs[8][128];
    __shared__ float hid[8][256];
    __shared__ float outs[8][128];
    int c0 = blockIdx.x * 8, tid = threadIdx.x;
    float ep = 1.f + epsp[0];
    for (int i = tid; i < 8 * 128; i += 256) {
        int c = i >> 7, d = i & 127;
        xs[c][d] = ep * high[(c0 + c) * 128 + d] + g_agg[(c0 + c) * 128 + d];
    }
    __syncthreads();
    {
        float acc[8];
        float bb = b1[tid];
#pragma unroll
        for (int c = 0; c < 8; c++) acc[c] = bb;
        for (int k = 0; k < 128; k++) {
            float w = w1[k * 256 + tid];
#pragma unroll
            for (int c = 0; c < 8; c++) acc[c] = fmaf(xs[c][k], w, acc[c]);
        }
#pragma unroll
        for (int c = 0; c < 8; c++) hid[c][tid] = geluf(acc[c]);
    }
    __syncthreads();
    if (tid < 128) {
        float a2[8];
        float bb2 = b2[tid];
#pragma unroll
        for (int c = 0; c < 8; c++) a2[c] = bb2;
        for (int k = 0; k < 256; k++) {
            float w = w2[k * 128 + tid];
#pragma unroll
            for (int c = 0; c < 8; c++) a2[c] = fmaf(hid[c][k], w, a2[c]);
        }
#pragma unroll
        for (int c = 0; c < 8; c++) outs[c][tid] = a2[c];
    }
    __syncthreads();
    int lane = tid & 31, warp = tid >> 5;
    float4 x = *(float4*)&outs[warp][lane * 4];
    float sum = warpSum(x.x + x.y + x.z + x.w);
    float sq = warpSum(x.x * x.x + x.y * x.y + x.z * x.z + x.w * x.w);
    float mean = sum * (1.f / D);
    float var = sq * (1.f / D) - mean * mean;
    float inv = rsqrtf(var + 1e-5f);
    float4 gg = *(const float4*)(lng + lane * 4);
    float4 bb = *(const float4*)(lnb + lane * 4);
    float4 y;
    y.x = (x.x - mean) * inv * gg.x + bb.x;
    y.y = (x.y - mean) * inv * gg.y + bb.y;
    y.z = (x.z - mean) * inv * gg.z + bb.z;
    y.w = (x.w - mean) * inv * gg.w + bb.w;
    *(float4*)(g_high_out + (size_t)(c0 + warp) * 128 + lane * 4) = y;
}

// ---------------- K4: 4-way projection GEMM, tf32 tensor cores ----------------
// A(131072x128) x {wq,wk,wv,wskip}(128x128) -> g_q/g_k/g_v/g_skip (NO bias;
// biases are folded into k_attn staging and k_lowout).
__global__ void __launch_bounds__(256) k_proj(const float* __restrict__ A,
        const float* __restrict__ wq, const float* __restrict__ wk,
        const float* __restrict__ wv, const float* __restrict__ ws) {
    extern __shared__ float sm[];
    float* As = sm;                      // [128][PAD_A]
    float* Bs0 = sm + 128 * PAD_A;       // [128][PAD_B]
    float* Bs1 = Bs0 + 128 * PAD_B;
    int tid = threadIdx.x;
    int warp = tid >> 5;
    int wm = warp >> 1, wn = warp & 1;   // 4 x 2 warp grid: 32-row x 64-col warp tiles
    size_t row0 = (size_t)blockIdx.x * 128;

    const float* Ws[4] = {wq, wk, wv, ws};
    float* Outs[4] = {g_q, g_k, g_v, g_skip};

    // cp.async stage A tile + first B
    for (int i = tid; i < 128 * 32; i += 256) {
        int r = i >> 5, ch = i & 31;
        cp16(As + r * PAD_A + ch * 4, A + row0 * 128 + r * 128 + ch * 4);
    }
    for (int i = tid; i < 128 * 32; i += 256) {
        int r = i >> 5, ch = i & 31;
        cp16(Bs0 + r * PAD_B + ch * 4, Ws[0] + r * 128 + ch * 4);
    }
    CP_COMMIT();
    CP_WAIT0();
    __syncthreads();

    typedef wmma::fragment<wmma::matrix_a, 16, 16, 8, wmma::precision::tf32, wmma::row_major> FragA;
    typedef wmma::fragment<wmma::matrix_b, 16, 16, 8, wmma::precision::tf32, wmma::row_major> FragB;
    typedef wmma::fragment<wmma::accumulator, 16, 16, 8, float> FragC;

    for (int w = 0; w < 4; ++w) {
        float* Bcur = (w & 1) ? Bs1 : Bs0;
        float* Bnext = (w & 1) ? Bs0 : Bs1;
        if (w < 3) {  // prefetch next weight while computing
            for (int i = tid; i < 128 * 32; i += 256) {
                int r = i >> 5, ch = i & 31;
                cp16(Bnext + r * PAD_B + ch * 4, Ws[w + 1] + r * 128 + ch * 4);
            }
            CP_COMMIT();
        }

        FragC acc[2][4];
#pragma unroll
        for (int i = 0; i < 2; i++)
#pragma unroll
            for (int j = 0; j < 4; j++) wmma::fill_fragment(acc[i][j], 0.f);

#pragma unroll
        for (int k0 = 0; k0 < 128; k0 += 8) {
            FragA a[2];
#pragma unroll
            for (int i = 0; i < 2; i++) {
                wmma::load_matrix_sync(a[i], As + (wm * 32 + i * 16) * PAD_A + k0, PAD_A);
#pragma unroll
                for (int t = 0; t < a[i].num_elements; t++)
                    a[i].x[t] = wmma::__float_to_tf32(a[i].x[t]);
            }
            FragB b[4];
#pragma unroll
            for (int j = 0; j < 4; j++) {
                wmma::load_matrix_sync(b[j], Bcur + k0 * PAD_B + wn * 64 + j * 16, PAD_B);
#pragma unroll
                for (int t = 0; t < b[j].num_elements; t++)
                    b[j].x[t] = wmma::__float_to_tf32(b[j].x[t]);
            }
#pragma unroll
            for (int i = 0; i < 2; i++)
#pragma unroll
                for (int j = 0; j < 4; j++)
                    wmma::mma_sync(acc[i][j], a[i], b[j], acc[i][j]);
        }

        float* Out = Outs[w];
#pragma unroll
        for (int i = 0; i < 2; i++)
#pragma unroll
            for (int j = 0; j < 4; j++)
                wmma::store_matrix_sync(Out + (row0 + wm * 32 + i * 16) * 128 + wn * 64 + j * 16,
                                        acc[i][j], 128, wmma::mem_row_major);
        if (w < 3) CP_WAIT0();
        __syncthreads();
    }
}

// ---------------- K5: per-cell GRN attention (adds q/k/v biases here) -------
__global__ void __launch_bounds__(256) k_attn(const float* __restrict__ bq,
                                              const float* __restrict__ bk,
                                              const float* __restrict__ bv) {
    extern __shared__ float sm[];
    float* qs = sm;
    float* ks = qs + N_GENES * 33;
    float* vs = ks + N_GENES * 33;
    int* soff = (int*)(vs + N_GENES * 33);
    int* ssrc = soff + 260;
    int c = blockIdx.x, tid = threadIdx.x;
    int lane = tid & 31, warp = tid >> 5;
    for (int i = tid; i <= N_GENES; i += 256) soff[i] = g_off[i];
    for (int i = tid; i < E_GRN; i += 256) ssrc[i] = g_srcs[i];
    const float* qb = g_q + (size_t)c * N_GENES * D;
    const float* kb = g_k + (size_t)c * N_GENES * D;
    const float* vb = g_v + (size_t)c * N_GENES * D;
    float* ob = g_attn + (size_t)c * N_GENES * D;

    for (int h = 0; h < HEADS; ++h) {
        __syncthreads();
        int hb = h * HD;
        float bqv = bq[hb + (tid & 31)];
        float bkv = bk[hb + (tid & 31)];
        float bvv = bv[hb + (tid & 31)];
        for (int i = tid; i < N_GENES * HD; i += 256) {
            int g = i >> 5, d = i & 31;
            qs[g * 33 + d] = qb[g * D + hb + d] + bqv;
            ks[g * 33 + d] = kb[g * D + hb + d] + bkv;
            vs[g * 33 + d] = vb[g * D + hb + d] + bvv;
        }
        __syncthreads();
        for (int g = warp; g < N_GENES; g += 8) {
            int o0 = soff[g], o1 = soff[g + 1];
            float out = 0.f;
            if (o1 > o0) {
                float m = -3.4e38f, s = 0.f, acc = 0.f;
                const float* qg = qs + g * 33;
                for (int base = o0; base < o1; base += 32) {
                    int cnt = min(32, o1 - base);
                    float logit = -3.4e38f;
                    int sj = 0;
                    if (lane < cnt) {
                        sj = ssrc[base + lane];
                        const float* kr = ks + sj * 33;
                        float t = 0.f;
#pragma unroll
                        for (int d = 0; d < HD; ++d) t = fmaf(qg[d], kr[d], t);
                        logit = t * 0.17677669529663689f;  // 1/sqrt(32)
                    }
                    float nm = fmaxf(m, warpMax(logit));
                    float sc = expf(m - nm);
                    s *= sc;
                    acc *= sc;
                    float e = (lane < cnt) ? expf(logit - nm) : 0.f;
                    s += warpSum(e);
                    for (int jj = 0; jj < cnt; ++jj) {
                        float ej = __shfl_sync(0xffffffffu, e, jj);
                        int sjj = __shfl_sync(0xffffffffu, sj, jj);
                        acc = fmaf(ej, vs[sjj * 33 + lane], acc);
                    }
                    m = nm;
                }
                out = acc / s;
            }
            ob[g * D + hb + lane] = out;
        }
    }
}

// ---------------- K6: low_out = LN(attn + skip + bskip), + gene sums -------
__global__ void k_lowout(const float* __restrict__ lng, const float* __restrict__ lnb,
                         const float* __restrict__ bsk) {
    __shared__ float part[4 * D];
    int c = blockIdx.x, tid = threadIdx.x;
    int lane = tid & 31, warp = tid >> 5;
    float4 gg = *(const float4*)(lng + lane * 4);
    float4 bb = *(const float4*)(lnb + lane * 4);
    float4 bs = *(const float4*)(bsk + lane * 4);
    float4 ls = make_float4(0.f, 0.f, 0.f, 0.f);
    const float* ab = g_attn + (size_t)c * N_GENES * D;
    const float* sb = g_skip + (size_t)c * N_GENES * D;
    float* lo = g_low_out + (size_t)c * N_GENES * D;
    for (int g = warp; g < N_GENES; g += 4) {
        float4 a = *(const float4*)(ab + g * D + lane * 4);
        float4 sk = *(const float4*)(sb + g * D + lane * 4);
        float4 x = make_float4(a.x + sk.x + bs.x, a.y + sk.y + bs.y,
                               a.z + sk.z + bs.z, a.w + sk.w + bs.w);
        float sum = warpSum(x.x + x.y + x.z + x.w);
        float sq = warpSum(x.x * x.x + x.y * x.y + x.z * x.z + x.w * x.w);
        float mean = sum * (1.f / D);
        float var = sq * (1.f / D) - mean * mean;
        float inv = rsqrtf(var + 1e-5f);
        float4 y;
        y.x = (x.x - mean) * inv * gg.x + bb.x;
        y.y = (x.y - mean) * inv * gg.y + bb.y;
        y.z = (x.z - mean) * inv * gg.z + bb.z;
        y.w = (x.w - mean) * inv * gg.w + bb.w;
        *(float4*)(lo + g * D + lane * 4) = y;
        ls.x += y.x; ls.y += y.y; ls.z += y.z; ls.w += y.w;
    }
    part[warp * D + lane * 4 + 0] = ls.x;
    part[warp * D + lane * 4 + 1] = ls.y;
    part[warp * D + lane * 4 + 2] = ls.z;
    part[warp * D + lane * 4 + 3] = ls.w;
    __syncthreads();
    if (tid < D) {
        float s = part[tid] + part[D + tid] + part[2 * D + tid] + part[3 * D + tid];
        g_gene_sum[c * D + tid] = s;
    }
}

// ---------------- K7: gene_agg = gelu(mean @ agg_w + agg_b) ----------------
__global__ void k_geneagg(const float* __restrict__ aw, const float* __restrict__ ab_) {
    __shared__ float m[D];
    int c = blockIdx.x, tid = threadIdx.x;
    m[tid] = g_gene_sum[c * D + tid] * (1.f / N_GENES);
    __syncthreads();
    float t = ab_[tid];
#pragma unroll 4
    for (int k = 0; k < D; ++k) t = fmaf(m[k], aw[k * D + tid], t);
    g_gene_agg[c * D + tid] = geluf(t);
}

// ---------------- K8: cross gating + high_new ----------------
__global__ void k_cross(const float* __restrict__ high_emb,
                        const float* __restrict__ cw, const float* __restrict__ cb,
                        const float* __restrict__ nhg, const float* __restrict__ nhb,
                        float* __restrict__ out_high) {
    __shared__ float hs[D], gs[D];
    __shared__ float r1[D], r2[D];
    int c = blockIdx.x, tid = threadIdx.x;
    float ho = g_high_out[c * D + tid];
    hs[tid] = ho;
    gs[tid] = g_gene_agg[c * D + tid];
    __syncthreads();
    float q1 = cb[tid], k1 = cb[D + tid], v1 = cb[2 * D + tid];
    float q2 = cb[3 * D + tid], k2 = cb[4 * D + tid], v2 = cb[5 * D + tid];
#pragma unroll 2
    for (int k = 0; k < D; ++k) {
        float hv = hs[k], gv = gs[k];
        const float* cwk = cw + k * D + tid;
        q1 = fmaf(hv, cwk[0], q1);
        k1 = fmaf(gv, cwk[16384], k1);
        v1 = fmaf(gv, cwk[32768], v1);
        q2 = fmaf(gv, cwk[49152], q2);
        k2 = fmaf(hv, cwk[65536], k2);
        v2 = fmaf(hv, cwk[81920], v2);
    }
    r1[tid] = q1 * k1;
    r2[tid] = q2 * k2;
    __syncthreads();
    for (int s = 64; s >= 1; s >>= 1) {
        if (tid < s) { r1[tid] += r1[tid + s]; r2[tid] += r2[tid + s]; }
        __syncthreads();
    }
    const float sc = 0.08838834764831845f;  // 128^-0.5
    float g1 = sigmoidf_(r1[0] * sc);
    float g2 = sigmoidf_(r2[0] * sc);
    g_low_cross[c * D + tid] = g2 * v2;
    float x = high_emb[c * D + tid] + ho + g1 * v1;
    __syncthreads();
    r1[tid] = x;
    r2[tid] = x * x;
    __syncthreads();
    for (int s = 64; s >= 1; s >>= 1) {
        if (tid < s) { r1[tid] += r1[tid + s]; r2[tid] += r2[tid + s]; }
        __syncthreads();
    }
    float mean = r1[0] * (1.f / D);
    float var = r2[0] * (1.f / D) - mean * mean;
    out_high[c * D + tid] = (x - mean) * rsqrtf(var + 1e-5f) * nhg[tid] + nhb[tid];
}

// ---------------- K9: low_new = LN(low_emb + low_out + low_cross) ----------
__global__ void k_lownew(const float* __restrict__ low_emb,
                         const float* __restrict__ nlg, const float* __restrict__ nlb,
                         float* __restrict__ out_low) {
    int tid = threadIdx.x, lane = tid & 31, warp = tid >> 5;
    int row = blockIdx.x * 8 + warp;
    int c = row >> 8;
    float4 gg = *(const float4*)(nlg + lane * 4);
    float4 bb = *(const float4*)(nlb + lane * 4);
    float4 le = *(const float4*)(low_emb + (size_t)row * D + lane * 4);
    float4 lo = *(const float4*)(g_low_out + (size_t)row * D + lane * 4);
    float4 lc = *(const float4*)(g_low_cross + c * D + lane * 4);
    float4 x = make_float4(le.x + lo.x + lc.x, le.y + lo.y + lc.y,
                           le.z + lo.z + lc.z, le.w + lo.w + lc.w);
    float sum = warpSum(x.x + x.y + x.z + x.w);
    float sq = warpSum(x.x * x.x + x.y * x.y + x.z * x.z + x.w * x.w);
    float mean = sum * (1.f / D);
    float var = sq * (1.f / D) - mean * mean;
    float inv = rsqrtf(var + 1e-5f);
    float4 y;
    y.x = (x.x - mean) * inv * gg.x + bb.x;
    y.y = (x.y - mean) * inv * gg.y + bb.y;
    y.z = (x.z - mean) * inv * gg.z + bb.z;
    y.w = (x.w - mean) * inv * gg.w + bb.w;
    *(float4*)(out_low + (size_t)row * D + lane * 4) = y;
}

// ---------------- host ----------------
extern "C" void kernel_launch(void* const* d_in, const int* in_sizes, int n_in,
                              void* d_out, int out_size) {
    const float* high = (const float*)d_in[0];
    const float* low = (const float*)d_in[1];
    const int* sp = (const int*)d_in[2];
    const int* grn = (const int*)d_in[3];
    const float* gin_w1 = (const float*)d_in[4];
    const float* gin_b1 = (const float*)d_in[5];
    const float* gin_w2 = (const float*)d_in[6];
    const float* gin_b2 = (const float*)d_in[7];
    const float* gin_eps = (const float*)d_in[8];
    const float* gin_lng = (const float*)d_in[9];
    const float* gin_lnb = (const float*)d_in[10];
    const float* wq = (const float*)d_in[11];
    const float* bq = (const float*)d_in[12];
    const float* wk = (const float*)d_in[13];
    const float* bk = (const float*)d_in[14];
    const float* wv = (const float*)d_in[15];
    const float* bv = (const float*)d_in[16];
    const float* wsk = (const float*)d_in[17];
    const float* bsk = (const float*)d_in[18];
    const float* tclng = (const float*)d_in[19];
    const float* tclnb = (const float*)d_in[20];
    const float* cw = (const float*)d_in[21];
    const float* cb = (const float*)d_in[22];
    const float* aw = (const float*)d_in[23];
    const float* ab = (const float*)d_in[24];
    const float* nhg = (const float*)d_in[25];
    const float* nhb = (const float*)d_in[26];
    const float* nlg = (const float*)d_in[27];
    const float* nlb = (const float*)d_in[28];

    float* out_high = (float*)d_out;
    float* out_low = out_high + N_CELLS * D;

    int smem_proj = (128 * PAD_A + 2 * 128 * PAD_B) * (int)sizeof(float);
    cudaFuncSetAttribute(k_proj, cudaFuncAttributeMaxDynamicSharedMemorySize, smem_proj);
    int smem_attn = (3 * N_GENES * 33) * (int)sizeof(float) + (260 + E_GRN) * (int)sizeof(int);
    cudaFuncSetAttribute(k_attn, cudaFuncAttributeMaxDynamicSharedMemorySize, smem_attn);

    k_zero<<<64, 1024>>>();
    k_scatter<<<(E_SP * D) / 256, 256>>>(high, sp);
    k_csr<<<1, 256>>>(grn);
    k_gin<<<N_CELLS / 8, 256>>>(high, gin_w1, gin_b1, gin_w2, gin_b2, gin_eps, gin_lng, gin_lnb);
    k_proj<<<(N_CELLS * N_GENES) / 128, 256, smem_proj>>>(low, wq, wk, wv, wsk);
    k_attn<<<N_CELLS, 256, smem_attn>>>(bq, bk, bv);
    k_lowout<<<N_CELLS, 128>>>(tclng, tclnb, bsk);
    k_geneagg<<<N_CELLS, 128>>>(aw, ab);
    k_cross<<<N_CELLS, 128>>>(high, cw, cb, nhg, nhb, out_high);
    k_lownew<<<(N_CELLS * N_GENES) / 8, 256>>>(low, nlg, nlb, out_low);
}